// round 7
// baseline (speedup 1.0000x reference)
#include <cuda_runtime.h>
#include <cuda_bf16.h>
#include <math.h>
#include <float.h>

// Fixed problem shapes
#define BB 32
#define NN 300
#define MM 50
#define NSLOT 10          // columns per lane: lanes 0..11 own 10, lanes 12..31 own 9

#define LAMBDA_POS 5.0
#define LAMBDA_CONF 2.0
#define LAMBDA_NOOBJ 0.5

#define FULLMASK 0xffffffffu

// Fixed-point scale 2^42 (resolution 2.3e-13). Bias +2.0 makes all quantized
// costs strictly positive so packed keys compare correctly as unsigned.
#define QSCALE 4398046511104.0   // 2^42
#define CBIAS  2.0

// Cross-block scratch (no cudaMalloc allowed)
__device__ double g_part[BB * 3];
__device__ int    g_done = 0;

__device__ __forceinline__ unsigned long long umin64(unsigned long long a, unsigned long long b) {
    return a < b ? a : b;
}
// warp argmin over packed u64 keys (key = (q<<9)|j, q >= 0): two u32 redux
__device__ __forceinline__ unsigned long long warp_min_key(unsigned long long mloc) {
    unsigned hi   = (unsigned)(mloc >> 32);
    unsigned hmin = __reduce_min_sync(FULLMASK, hi);
    unsigned lo   = (hi == hmin) ? (unsigned)mloc : 0xFFFFFFFFu;
    unsigned lmin = __reduce_min_sync(FULLMASK, lo);
    return ((unsigned long long)hmin << 32) | lmin;
}
__device__ __forceinline__ double softplus_d(double x) {
    return fmax(x, 0.0) + log1p(exp(-fabs(x)));
}

// Dynamic smem layout (8-byte entries first)
//   sq    [MM*NN]  i64  pre-packed cost keys: (q<<9) | j   (q > 0)
//   spq   [NN]     i64  exact shortest (quantized) for dual updates
//   urq   [NN]     i64  u[row4col[j]] cache (quantized)
//   suq   [MM]     i64  dual u (quantized)
//   sgt   [MM*2]   f32  staged gt centroids
//   pb    [NN]     i32  pathback
//   r4c   [NN]     i32  row4col (-1 = free)
//   c4r   [MM]     i32  col4row (-1 = unassigned)
#define SMEM_QWORDS (MM * NN + NN + NN + MM)
#define SMEM_BYTES  (SMEM_QWORDS * 8 + MM * 2 * 4 + (NN + NN + MM) * 4)

__global__ void __launch_bounds__(32, 1)
detloss_kernel(const float* __restrict__ pred_c,  // [B,N,2]
               const float* __restrict__ conf,    // [B,N]
               const float* __restrict__ gt_c,    // [B,M,2]
               float* __restrict__ out)           // [5]
{
    const int b    = blockIdx.x;
    const int lane = threadIdx.x;

    const float* pc = pred_c + b * NN * 2;
    const float* cf = conf   + b * NN;
    const float* gc = gt_c   + b * MM * 2;

    extern __shared__ long long dyn[];
    long long* sq   = dyn;                  // [MM][NN] packed cost keys
    long long* spq  = sq + MM * NN;         // [NN]
    long long* urq  = spq + NN;             // [NN]
    long long* suq  = urq + NN;             // [MM]
    float*     sgt  = (float*)(suq + MM);   // [MM*2]
    int*       pb   = (int*)(sgt + MM * 2); // [NN]
    int*       r4c  = pb + NN;              // [NN]
    int*       c4r  = r4c + NN;             // [MM]

    // ---- Stage gt into smem ----
    for (int t = lane; t < MM * 2; t += 32) sgt[t] = gc[t];
    for (int j = lane; j < NN; j += 32) { r4c[j] = -1; urq[j] = 0; }
    for (int m = lane; m < MM; m += 32) { suq[m] = 0; c4r[m] = -1; }
    __syncwarp();

    // ---- Build packed cost keys: q = rn((5*L1 - sigmoid + 2)*2^42) > 0 ----
    // Column j is built AND consumed by lane (j % 32): no sync needed on sq.
    #pragma unroll
    for (int k = 0; k < NSLOT; k++) {
        int j = k * 32 + lane;
        if (j < NN) {
            double x   = (double)cf[j];
            double sig = 1.0 / (1.0 + exp(-x));
            double px  = (double)pc[2 * j];
            double py  = (double)pc[2 * j + 1];
            for (int m = 0; m < MM; m++) {
                double dx = fabs(px - (double)sgt[2 * m]);
                double dy = fabs(py - (double)sgt[2 * m + 1]);
                double c  = 5.0 * (dx + dy) - sig + CBIAS;   // > 0 always
                long long q = __double2ll_rn(c * QSCALE);
                sq[m * NN + j] = (q << 9) | (long long)j;
            }
        }
    }

    // per-lane register duals for owned columns (quantized)
    long long vq[NSLOT];
    #pragma unroll
    for (int k = 0; k < NSLOT; k++) vq[k] = 0;
    const unsigned validMask = (lane < 12) ? 0x3FFu : 0x1FFu;

    // ==== Phase 1: row reduction + greedy assignment (all-integer) ====
    for (int i = 0; i < MM; i++) {
        const long long* crow = sq + i * NN;
        unsigned long long best = ~0ULL;
        #pragma unroll
        for (int k = 0; k < NSLOT; k++) {
            if (validMask & (1u << k)) {
                best = umin64(best, (unsigned long long)crow[k * 32 + lane]);
            }
        }
        unsigned long long mk = warp_min_key(best);
        int       jmin = (int)(mk & 511u);
        long long rmin = (long long)(mk >> 9);
        suq[i] = rmin;                       // same value from all lanes
        if (r4c[jmin] < 0) {
            r4c[jmin] = i;
            c4r[i]    = jmin;
            urq[jmin] = rmin;
        }
    }
    __syncwarp();

    // ==== Phase 2: shortest augmenting path (all-integer) ====
    // JV invariant u[i]+v[j] <= c[i][j] holds EXACTLY in integer arithmetic,
    // so all shortest-path keys are nonnegative -> unsigned compares valid.
    for (int cur = 0; cur < MM; cur++) {
        if (c4r[cur] >= 0) continue;

        unsigned long long skey[NSLOT];
        #pragma unroll
        for (int k = 0; k < NSLOT; k++) skey[k] = ~0ULL;
        unsigned rem = validMask;
        unsigned remRound = 0;
        unsigned long long SR = 1ULL << cur;

        int       i    = cur;
        long long uiq  = suq[cur];
        long long minq = 0;
        int       sink;

        while (true) {
            // offset (minval - u[i] - v[k]) << 9 ; low 9 bits zero so the
            // per-column add preserves the packed column index exactly.
            long long pq = minq - uiq;
            const long long* crow = sq + i * NN;

            #pragma unroll
            for (int k = 0; k < NSLOT; k++) {
                if (rem & (1u << k)) {
                    int j = k * 32 + lane;
                    long long off = (pq - vq[k]) << 9;
                    unsigned long long ck = (unsigned long long)(crow[j] + off);
                    if (ck < skey[k]) {
                        skey[k] = ck;
                        spq[j]  = (long long)(ck >> 9);  // exact shortest value
                        pb[j]   = i;
                    }
                }
            }
            unsigned long long a0 = umin64(skey[0], skey[1]);
            unsigned long long a1 = umin64(skey[2], skey[3]);
            unsigned long long a2 = umin64(skey[4], skey[5]);
            unsigned long long a3 = umin64(skey[6], skey[7]);
            unsigned long long a4 = umin64(skey[8], skey[9]);
            unsigned long long mloc = umin64(umin64(umin64(a0, a1), umin64(a2, a3)), a4);

            unsigned long long mk = warp_min_key(mloc);
            int jst = (int)(mk & 511u);
            minq    = (long long)(mk >> 9);

            if ((jst & 31) == lane) {        // owner retires its column locally
                int slot = jst >> 5;
                rem      &= ~(1u << slot);
                remRound |=  (1u << slot);
                #pragma unroll
                for (int k = 0; k < NSLOT; k++) if (k == slot) skey[k] = ~0ULL;
            }

            int       rr = r4c[jst];
            long long uu = urq[jst];
            if (rr < 0) { sink = jst; break; }
            i   = rr;
            uiq = uu;
            SR |= 1ULL << i;
        }

        __syncwarp();

        // dual updates (exact integer)
        for (int m = lane; m < MM; m += 32) {
            if (m == cur) {
                suq[m] += minq;
            } else if ((SR >> m) & 1) {
                suq[m] += minq - spq[c4r[m]];
            }
        }
        #pragma unroll
        for (int k = 0; k < NSLOT; k++) {
            if (remRound & (1u << k)) {
                int j = k * 32 + lane;
                vq[k] -= (minq - spq[j]);
            }
        }
        __syncwarp();

        // augment (lane 0)
        if (lane == 0) {
            int j = sink;
            while (true) {
                int ii = pb[j];
                r4c[j] = ii;
                int t = c4r[ii];
                c4r[ii] = j;
                j = t;
                if (ii == cur) break;
            }
        }
        __syncwarp();

        // refresh urq cache for matched columns
        for (int m = lane; m < MM; m += 32) {
            int jm = c4r[m];
            if (jm >= 0) urq[jm] = suq[m];
        }
        __syncwarp();
    }

    // ==== Loss partials (exact fp64 from original inputs) ====
    double pos = 0.0, obj = 0.0, noobj = 0.0;
    for (int m = lane; m < MM; m += 32) {
        int j = c4r[m];
        double dx = fabs((double)pc[2 * j]     - (double)sgt[2 * m]);
        double dy = fabs((double)pc[2 * j + 1] - (double)sgt[2 * m + 1]);
        pos += dx + dy;
        obj += softplus_d(-(double)cf[j]);
    }
    #pragma unroll
    for (int k = 0; k < NSLOT; k++) {
        int j = k * 32 + lane;
        if (j < NN && r4c[j] < 0)
            noobj += softplus_d((double)cf[j]);
    }
    #pragma unroll
    for (int off = 16; off; off >>= 1) {
        pos   += __shfl_xor_sync(FULLMASK, pos,   off);
        obj   += __shfl_xor_sync(FULLMASK, obj,   off);
        noobj += __shfl_xor_sync(FULLMASK, noobj, off);
    }
    int islast = 0;
    if (lane == 0) {
        g_part[b * 3 + 0] = pos   / (double)(MM * 2);
        g_part[b * 3 + 1] = obj   / (double)MM;
        g_part[b * 3 + 2] = noobj / (double)(NN - MM);
        __threadfence();
        int t = atomicAdd(&g_done, 1);
        islast = (t == BB - 1);
    }
    islast = __shfl_sync(FULLMASK, islast, 0);

    if (islast) {  // fused finalize: last block reduces the 32 partials
        __threadfence();
        double p = 0.0, o = 0.0, q = 0.0;
        if (lane < BB) {
            p = g_part[lane * 3 + 0];
            o = g_part[lane * 3 + 1];
            q = g_part[lane * 3 + 2];
        }
        #pragma unroll
        for (int off = 16; off; off >>= 1) {
            p += __shfl_xor_sync(FULLMASK, p, off);
            o += __shfl_xor_sync(FULLMASK, o, off);
            q += __shfl_xor_sync(FULLMASK, q, off);
        }
        if (lane == 0) {
            float lp = (float)(LAMBDA_POS   * p / (double)BB);
            float lo = (float)(LAMBDA_CONF  * o / (double)BB);
            float ln = (float)(LAMBDA_NOOBJ * q / (double)BB);
            out[0] = lp;
            out[1] = lo;
            out[2] = ln;
            out[3] = lp + lo + ln;
            out[4] = (float)MM;
            g_done = 0;   // self-reset for next graph replay
        }
    }
}

extern "C" void kernel_launch(void* const* d_in, const int* in_sizes, int n_in,
                              void* d_out, int out_size)
{
    const float* pred_c = (const float*)d_in[0];
    const float* conf   = (const float*)d_in[2];
    const float* gt_c   = (const float*)d_in[3];
    float* out = (float*)d_out;

    cudaFuncSetAttribute(detloss_kernel,
                         cudaFuncAttributeMaxDynamicSharedMemorySize, SMEM_BYTES);
    detloss_kernel<<<BB, 32, SMEM_BYTES>>>(pred_c, conf, gt_c, out);
}